// round 5
// baseline (speedup 1.0000x reference)
#include <cuda_runtime.h>
#include <cuda_bf16.h>
#include <mma.h>

using namespace nvcuda;

// ---------------------------------------------------------------------------
// Problem constants
// ---------------------------------------------------------------------------
#define NB      4
#define CDIM    64
#define HW      65536          // 256*256
#define NWIN    1024           // 4 * 16 * 16
#define DIN     128            // d_inner
#define NDBL    36             // dt_rank + 2*d_state
#define M_TOT   (NWIN * 256)   // 262144 token positions

// ---------------------------------------------------------------------------
// Scratch (static device globals — allocation-free per harness rules)
// ---------------------------------------------------------------------------
__device__ __align__(16) __nv_bfloat16 g_xw [M_TOT * CDIM];  // LN2 out, windowed
__device__ __align__(16) __nv_bfloat16 g_xz [M_TOT * 256];   // in_proj out (xm|z)
__device__ __align__(16) __nv_bfloat16 g_xc [M_TOT * DIN];   // conv+silu out
__device__ __align__(16) float         g_dbl[M_TOT * NDBL];  // x_proj out (dt|B|C)
__device__ __align__(16) __nv_bfloat16 g_y  [M_TOT * DIN];   // scan+gate out
__device__ __align__(16) float         g_x2 [NB * CDIM * HW];// x + attn (NCHW)
__device__ __align__(16) __nv_bfloat16 g_y2 [M_TOT * CDIM];  // LN3 out, pos-major
__device__ __align__(16) __nv_bfloat16 g_hid[M_TOT * 256];   // ffn_in out
__device__ __align__(16) __nv_bfloat16 g_g  [M_TOT * DIN];   // gelu(h1)*h2
__device__ float g_Atab[DIN * 16];
__device__ int   g_flag;

// ---------------------------------------------------------------------------
// prep: A table + structure flag (A[d][s] == -(s+1) fast path)
// ---------------------------------------------------------------------------
__global__ void prep_kernel(const float* __restrict__ alog,
                            float* __restrict__ Atab, int* __restrict__ flag)
{
    __shared__ int ok_s;
    if (threadIdx.x == 0) ok_s = 1;
    __syncthreads();
    bool ok = true;
    for (int i = threadIdx.x; i < DIN * 16; i += 256) {
        float a = -expf(alog[i]);
        Atab[i] = a;
        int s = i & 15;
        if (fabsf(a + (float)(s + 1)) > 1e-3f * (float)(s + 1)) ok = false;
    }
    if (!ok) atomicAnd(&ok_s, 0);
    __syncthreads();
    if (threadIdx.x == 0) *flag = ok_s;
}

// ---------------------------------------------------------------------------
// Channel LayerNorm -> bf16.  Vectorized loads (float4) + packed bf16x2 stores.
// mode 0: windowed layout (win*256+l, c).  mode 1: pos-major (b*65536+hw, c).
// ---------------------------------------------------------------------------
__global__ void __launch_bounds__(256) ln_kernel(
    const float* __restrict__ x, const float* __restrict__ gam,
    const float* __restrict__ bet, __nv_bfloat16* __restrict__ out, int mode)
{
    __shared__ float s[64][65];
    __shared__ float mu[64], rs[64];
    int tid  = threadIdx.x;
    int blk  = blockIdx.x;
    int bimg = blk >> 10;
    int rem  = blk & 1023;
    int h    = rem >> 2;
    int w0   = (rem & 3) << 6;
    const float* xb = x + ((bimg * CDIM) << 16) + (h << 8) + w0;

    // 64x64 tile: 1024 float4 loads, 4 per thread
#pragma unroll
    for (int i = 0; i < 4; i++) {
        int idx = i * 256 + tid;          // 0..1023
        int c  = idx >> 4;                // channel
        int p4 = (idx & 15) << 2;         // position group
        float4 v = *(const float4*)&xb[(c << 16) + p4];
        s[p4 + 0][c] = v.x; s[p4 + 1][c] = v.y;
        s[p4 + 2][c] = v.z; s[p4 + 3][c] = v.w;
    }
    __syncthreads();
    if (tid < 64) {
        float sum = 0.f, sq = 0.f;
#pragma unroll
        for (int c = 0; c < 64; c++) { float v = s[tid][c]; sum += v; sq += v * v; }
        float m = sum * (1.f / 64.f);
        float var = sq * (1.f / 64.f) - m * m;
        mu[tid] = m;
        rs[tid] = rsqrtf(var + 1e-5f);
    }
    __syncthreads();
    // packed bf16x2 stores: 2048 pairs, 8 per thread
#pragma unroll
    for (int i = 0; i < 8; i++) {
        int idx = i * 256 + tid;          // 0..2047
        int p  = idx >> 5;                // position in tile
        int cp = (idx & 31) << 1;         // channel pair
        float m_ = mu[p], r_ = rs[p];
        float v0 = (s[p][cp]     - m_) * r_ * gam[cp]     + bet[cp];
        float v1 = (s[p][cp + 1] - m_) * r_ * gam[cp + 1] + bet[cp + 1];
        int wg = w0 + p;
        int pos;
        if (mode == 0) {
            int win = (bimg << 8) + ((h >> 4) << 4) + (wg >> 4);
            int l   = ((h & 15) << 4) + (wg & 15);
            pos = (win << 8) + l;
        } else {
            pos = (bimg << 16) + (h << 8) + wg;
        }
        *(__nv_bfloat162*)&out[(pos << 6) + cp] = __floats2bfloat162_rn(v0, v1);
    }
}

// ---------------------------------------------------------------------------
// Tensor-core GEMM: C[M,N] = A[M,K](bf16) @ W[N,K]^T(fp32->bf16)
// Block tile 128x64, 256 threads (8 warps, 4x2), warp tile 32x32, BK=64.
// ---------------------------------------------------------------------------
template<int EP, bool OUTBF>
__global__ void __launch_bounds__(256) gemm_tc(
    const __nv_bfloat16* __restrict__ A, const float* __restrict__ W,
    void* __restrict__ Cout, const float* __restrict__ res,
    int M, int N, int K, int ldc)
{
    __shared__ __align__(16) unsigned char smem_raw[34816];
    __nv_bfloat16* As = (__nv_bfloat16*)smem_raw;   // [128][72]
    __nv_bfloat16* Ws = As + 128 * 72;              // [64][72]
    float* epi = (float*)smem_raw;                  // [128][68]
    static_assert(128 * 72 * 2 + 64 * 72 * 2 <= 34816, "operand smem");
    static_assert(128 * 68 * 4 <= 34816, "epilogue smem");

    int tid = threadIdx.x;
    int wid = tid >> 5;
    int wm = wid >> 1, wn = wid & 1;
    int m0 = blockIdx.x * 128;
    int n0 = blockIdx.y * 64;

    wmma::fragment<wmma::accumulator, 16, 16, 16, float> c[2][2];
#pragma unroll
    for (int i = 0; i < 2; i++)
#pragma unroll
        for (int j = 0; j < 2; j++) wmma::fill_fragment(c[i][j], 0.f);

    for (int k0 = 0; k0 < K; k0 += 64) {
#pragma unroll
        for (int i = 0; i < 4; i++) {
            int idx = tid + i * 256;
            int r = idx >> 3, v = idx & 7;
            *(uint4*)&As[r * 72 + v * 8] =
                *(const uint4*)&A[(m0 + r) * K + k0 + v * 8];
        }
#pragma unroll
        for (int i = 0; i < 4; i++) {
            int idx = tid + i * 256;
            int r = idx >> 4, v = idx & 15;
            float4 f = make_float4(0.f, 0.f, 0.f, 0.f);
            if (n0 + r < N) f = *(const float4*)&W[(n0 + r) * K + k0 + v * 4];
            __nv_bfloat16* dst = &Ws[r * 72 + v * 4];
            dst[0] = __float2bfloat16(f.x);
            dst[1] = __float2bfloat16(f.y);
            dst[2] = __float2bfloat16(f.z);
            dst[3] = __float2bfloat16(f.w);
        }
        __syncthreads();
#pragma unroll
        for (int kk = 0; kk < 64; kk += 16) {
            wmma::fragment<wmma::matrix_a, 16, 16, 16, __nv_bfloat16, wmma::row_major> a[2];
            wmma::fragment<wmma::matrix_b, 16, 16, 16, __nv_bfloat16, wmma::col_major> b[2];
#pragma unroll
            for (int i = 0; i < 2; i++)
                wmma::load_matrix_sync(a[i], &As[(wm * 32 + i * 16) * 72 + kk], 72);
#pragma unroll
            for (int j = 0; j < 2; j++)
                wmma::load_matrix_sync(b[j], &Ws[(wn * 32 + j * 16) * 72 + kk], 72);
#pragma unroll
            for (int i = 0; i < 2; i++)
#pragma unroll
                for (int j = 0; j < 2; j++)
                    wmma::mma_sync(c[i][j], a[i], b[j], c[i][j]);
        }
        __syncthreads();
    }

#pragma unroll
    for (int i = 0; i < 2; i++)
#pragma unroll
        for (int j = 0; j < 2; j++)
            wmma::store_matrix_sync(&epi[(wm * 32 + i * 16) * 68 + wn * 32 + j * 16],
                                    c[i][j], 68, wmma::mem_row_major);
    __syncthreads();

    if (EP == 0) {
        if (OUTBF) {
            __nv_bfloat16* Cb = (__nv_bfloat16*)Cout;
#pragma unroll
            for (int i = 0; i < 16; i++) {
                int idx = tid + i * 256;
                int r = idx >> 5, cp = (idx & 31) * 2;
                __nv_bfloat162 pk = __floats2bfloat162_rn(epi[r * 68 + cp],
                                                          epi[r * 68 + cp + 1]);
                *(__nv_bfloat162*)&Cb[(m0 + r) * ldc + n0 + cp] = pk;
            }
        } else {
            float* Cf = (float*)Cout;
#pragma unroll
            for (int i = 0; i < 32; i++) {
                int idx = tid + i * 256;
                int r = idx >> 6, cn = idx & 63;
                int n = n0 + cn;
                if (n < N) Cf[(m0 + r) * ldc + n] = epi[r * 68 + cn];
            }
        }
    } else {
        float* Cf = (float*)Cout;
#pragma unroll
        for (int i = 0; i < 32; i++) {
            int idx = tid + i * 256;
            int n = idx >> 7;
            int r = idx & 127;
            float v = epi[r * 68 + n];
            int m = m0 + r;
            int addr;
            if (EP == 1) {
                int win = m >> 8, l = m & 255;
                int b = win >> 8, widx = win & 255;
                int h = ((widx >> 4) << 4) + (l >> 4);
                int w = ((widx & 15) << 4) + (l & 15);
                addr = ((b * CDIM + n) << 16) + (h << 8) + w;
            } else {
                int b = m >> 16, hw = m & 65535;
                addr = ((b * CDIM + n) << 16) + hw;
            }
            Cf[addr] = res[addr] + v;
        }
    }
}

// ---------------------------------------------------------------------------
// Depthwise causal conv1d (k=4, pad 3) + bias + SiLU.
// One thread = 8 contiguous channels of one position (uint4 = 8x bf16).
// ---------------------------------------------------------------------------
__global__ void __launch_bounds__(256) conv_kernel(
    const __nv_bfloat16* __restrict__ xz, const float* __restrict__ cw,
    const float* __restrict__ cb, __nv_bfloat16* __restrict__ xc)
{
    int gid = blockIdx.x * 256 + threadIdx.x;   // M_TOT*16 total
    int dg = gid & 15;                          // channel group (8 ch)
    int m  = gid >> 4;
    int t  = m & 255;
    int d0 = dg << 3;

    float acc[8];
#pragma unroll
    for (int q = 0; q < 8; q++) acc[q] = cb[d0 + q];

#pragma unroll
    for (int j = 0; j < 4; j++) {
        if (t - 3 + j >= 0) {
            uint4 raw = *(const uint4*)&xz[((m - 3 + j) << 8) + d0];
            const __nv_bfloat162* pk = (const __nv_bfloat162*)&raw;
#pragma unroll
            for (int q2 = 0; q2 < 4; q2++) {
                float2 f = __bfloat1622float2(pk[q2]);
                acc[q2 * 2 + 0] = fmaf(cw[((d0 + q2 * 2 + 0) << 2) + j], f.x, acc[q2 * 2 + 0]);
                acc[q2 * 2 + 1] = fmaf(cw[((d0 + q2 * 2 + 1) << 2) + j], f.y, acc[q2 * 2 + 1]);
            }
        }
    }

    uint4 outv;
    __nv_bfloat162* op = (__nv_bfloat162*)&outv;
#pragma unroll
    for (int q2 = 0; q2 < 4; q2++) {
        float a0 = acc[q2 * 2], a1 = acc[q2 * 2 + 1];
        float s0 = __fdividef(a0, 1.f + __expf(-a0));
        float s1 = __fdividef(a1, 1.f + __expf(-a1));
        op[q2] = __floats2bfloat162_rn(s0, s1);
    }
    *(uint4*)&xc[(m << 7) + d0] = outv;
}

// ---------------------------------------------------------------------------
// Selective scan + fused dt_proj/softplus + D skip + SiLU(z) gate.
// ---------------------------------------------------------------------------
__global__ void __launch_bounds__(128) scan_kernel(
    const float* __restrict__ dbl, const __nv_bfloat16* __restrict__ xc,
    const __nv_bfloat16* __restrict__ xz, const float* __restrict__ dtw,
    const float* __restrict__ dtb, const float* __restrict__ Dv,
    const float* __restrict__ Atab, const int* __restrict__ flagp,
    __nv_bfloat16* __restrict__ yout)
{
    int win = blockIdx.x;
    int d = threadIdx.x;
    int fl = *flagp;
    float Dd = Dv[d];
    float4 wv = *(const float4*)&dtw[d << 2];
    float bb = dtb[d];
    float h[16];
#pragma unroll
    for (int s = 0; s < 16; s++) h[s] = 0.f;
    int mbase = win << 8;

    for (int t = 0; t < 256; t++) {
        int m = mbase + t;
        const float* row = dbl + m * NDBL;
        float4 q = *(const float4*)row;
        float pre = bb + q.x * wv.x + q.y * wv.y + q.z * wv.z + q.w * wv.w;
        float dtv = (pre > 15.f) ? pre : log1pf(__expf(pre));
        float u  = __bfloat162float(xc[(m << 7) + d]);
        float zv = __bfloat162float(xz[(m << 8) + 128 + d]);
        float4 B0 = *(const float4*)(row + 4);
        float4 B1 = *(const float4*)(row + 8);
        float4 B2 = *(const float4*)(row + 12);
        float4 B3 = *(const float4*)(row + 16);
        float4 C0 = *(const float4*)(row + 20);
        float4 C1 = *(const float4*)(row + 24);
        float4 C2 = *(const float4*)(row + 28);
        float4 C3 = *(const float4*)(row + 32);
        float Bv[16] = {B0.x,B0.y,B0.z,B0.w, B1.x,B1.y,B1.z,B1.w,
                        B2.x,B2.y,B2.z,B2.w, B3.x,B3.y,B3.z,B3.w};
        float Cv[16] = {C0.x,C0.y,C0.z,C0.w, C1.x,C1.y,C1.z,C1.w,
                        C2.x,C2.y,C2.z,C2.w, C3.x,C3.y,C3.z,C3.w};
        float dtu = dtv * u;
        float yv = 0.f;
        if (fl) {
            float r = __expf(-dtv);
            float p = r;
#pragma unroll
            for (int s = 0; s < 16; s++) {
                h[s] = h[s] * p + dtu * Bv[s];
                yv += h[s] * Cv[s];
                p *= r;
            }
        } else {
#pragma unroll
            for (int s = 0; s < 16; s++) {
                float dec = __expf(dtv * Atab[(d << 4) + s]);
                h[s] = h[s] * dec + dtu * Bv[s];
                yv += h[s] * Cv[s];
            }
        }
        yv += u * Dd;
        float sg = __fdividef(1.f, 1.f + __expf(-zv));
        yout[(m << 7) + d] = __float2bfloat16(yv * zv * sg);
    }
}

// ---------------------------------------------------------------------------
// Depthwise 3x3 SAME conv + exact-GELU gate.
// Thread = 4 h1-channels + paired 4 h2-channels of one position (uint2 loads).
// Block = 256 threads = 8 positions; dww staged in smem ([c][k] linear copy).
// ---------------------------------------------------------------------------
__global__ void __launch_bounds__(256) dw_kernel(
    const __nv_bfloat16* __restrict__ hid, const float* __restrict__ dww,
    __nv_bfloat16* __restrict__ gout)
{
    __shared__ float wsm[256 * 9];
    int tid = threadIdx.x;
#pragma unroll
    for (int i = 0; i < 9; i++) wsm[i * 256 + tid] = dww[i * 256 + tid];
    __syncthreads();

    int gid = blockIdx.x * 256 + tid;     // M_TOT*32 total
    int j = gid & 31;                     // channel quad index
    int m = gid >> 5;
    int c0 = j << 2;                      // h1 channels c0..c0+3
    int b = m >> 16, hw = m & 65535;
    int h = hw >> 8, w = hw & 255;

    float a1[4] = {0.f, 0.f, 0.f, 0.f};
    float a2[4] = {0.f, 0.f, 0.f, 0.f};

#pragma unroll
    for (int dy = 0; dy < 3; dy++) {
        int hh = h + dy - 1;
        if (hh < 0 || hh > 255) continue;
#pragma unroll
        for (int dx = 0; dx < 3; dx++) {
            int ww = w + dx - 1;
            if (ww < 0 || ww > 255) continue;
            int mm = (b << 16) + (hh << 8) + ww;
            const __nv_bfloat16* rowp = hid + (mm << 8);
            uint2 r1 = *(const uint2*)&rowp[c0];
            uint2 r2 = *(const uint2*)&rowp[c0 + 128];
            float2 f1a = __bfloat1622float2(((const __nv_bfloat162*)&r1)[0]);
            float2 f1b = __bfloat1622float2(((const __nv_bfloat162*)&r1)[1]);
            float2 f2a = __bfloat1622float2(((const __nv_bfloat162*)&r2)[0]);
            float2 f2b = __bfloat1622float2(((const __nv_bfloat162*)&r2)[1]);
            int k = dy * 3 + dx;
            a1[0] = fmaf(wsm[(c0 + 0) * 9 + k], f1a.x, a1[0]);
            a1[1] = fmaf(wsm[(c0 + 1) * 9 + k], f1a.y, a1[1]);
            a1[2] = fmaf(wsm[(c0 + 2) * 9 + k], f1b.x, a1[2]);
            a1[3] = fmaf(wsm[(c0 + 3) * 9 + k], f1b.y, a1[3]);
            a2[0] = fmaf(wsm[(c0 + 128) * 9 + k], f2a.x, a2[0]);
            a2[1] = fmaf(wsm[(c0 + 129) * 9 + k], f2a.y, a2[1]);
            a2[2] = fmaf(wsm[(c0 + 130) * 9 + k], f2b.x, a2[2]);
            a2[3] = fmaf(wsm[(c0 + 131) * 9 + k], f2b.y, a2[3]);
        }
    }

    uint2 outv;
    __nv_bfloat162* op = (__nv_bfloat162*)&outv;
#pragma unroll
    for (int q = 0; q < 2; q++) {
        float g0 = 0.5f * a1[q * 2]     * (1.f + erff(a1[q * 2]     * 0.70710678118f));
        float g1 = 0.5f * a1[q * 2 + 1] * (1.f + erff(a1[q * 2 + 1] * 0.70710678118f));
        op[q] = __floats2bfloat162_rn(g0 * a2[q * 2], g1 * a2[q * 2 + 1]);
    }
    *(uint2*)&gout[(m << 7) + c0] = outv;
}

// ---------------------------------------------------------------------------
// launch
// ---------------------------------------------------------------------------
extern "C" void kernel_launch(void* const* d_in, const int* in_sizes, int n_in,
                              void* d_out, int out_size)
{
    (void)in_sizes; (void)n_in; (void)out_size;
    const float* x     = (const float*)d_in[0];
    const float* ln2w  = (const float*)d_in[1];
    const float* ln2b  = (const float*)d_in[2];
    const float* ln3w  = (const float*)d_in[3];
    const float* ln3b  = (const float*)d_in[4];
    const float* inpw  = (const float*)d_in[5];
    const float* convw = (const float*)d_in[6];
    const float* convb = (const float*)d_in[7];
    const float* xpw   = (const float*)d_in[8];
    const float* dtw   = (const float*)d_in[9];
    const float* dtb   = (const float*)d_in[10];
    const float* alog  = (const float*)d_in[11];
    const float* Dv    = (const float*)d_in[12];
    const float* outw  = (const float*)d_in[13];
    const float* fiw   = (const float*)d_in[14];
    const float* fdw   = (const float*)d_in[15];
    const float* fow   = (const float*)d_in[16];
    float* out = (float*)d_out;

    __nv_bfloat16 *xw, *xz, *xc, *yb, *y2, *hid, *gg;
    float *dbl, *x2, *Atab;
    int* flag;
    cudaGetSymbolAddress((void**)&xw,  g_xw);
    cudaGetSymbolAddress((void**)&xz,  g_xz);
    cudaGetSymbolAddress((void**)&xc,  g_xc);
    cudaGetSymbolAddress((void**)&dbl, g_dbl);
    cudaGetSymbolAddress((void**)&yb,  g_y);
    cudaGetSymbolAddress((void**)&x2,  g_x2);
    cudaGetSymbolAddress((void**)&y2,  g_y2);
    cudaGetSymbolAddress((void**)&hid, g_hid);
    cudaGetSymbolAddress((void**)&gg,  g_g);
    cudaGetSymbolAddress((void**)&Atab, g_Atab);
    cudaGetSymbolAddress((void**)&flag, g_flag);

    prep_kernel<<<1, 256>>>(alog, Atab, flag);

    // LN2 + window partition -> bf16
    ln_kernel<<<4096, 256>>>(x, ln2w, ln2b, xw, 0);

    // in_proj: (262144,64) @ (256,64)^T -> xz (bf16)
    {
        dim3 g(M_TOT / 128, 4);
        gemm_tc<0, true><<<g, 256>>>(xw, inpw, xz, nullptr, M_TOT, 256, 64, 256);
    }

    // depthwise causal conv1d + silu (8 ch / thread)
    conv_kernel<<<M_TOT * 16 / 256, 256>>>(xz, convw, convb, xc);

    // x_proj: (262144,128) @ (36,128)^T -> dbl (fp32)
    {
        dim3 g(M_TOT / 128, 1);
        gemm_tc<0, false><<<g, 256>>>(xc, xpw, dbl, nullptr, M_TOT, NDBL, 128, NDBL);
    }

    // selective scan (fused dt_proj+softplus) + D skip + silu(z) gate
    scan_kernel<<<NWIN, 128>>>(dbl, xc, xz, dtw, dtb, Dv, Atab, flag, yb);

    // out_proj + un-window + residual -> x2 (fp32)
    {
        dim3 g(M_TOT / 128, 1);
        gemm_tc<1, false><<<g, 256>>>(yb, outw, x2, x, M_TOT, 64, 128, 0);
    }

    // LN3 -> y2 (pos-major, bf16)
    ln_kernel<<<4096, 256>>>(x2, ln3w, ln3b, y2, 1);

    // ffn_in: (262144,64) @ (256,64)^T -> hid (bf16)
    {
        dim3 g(M_TOT / 128, 4);
        gemm_tc<0, true><<<g, 256>>>(y2, fiw, hid, nullptr, M_TOT, 256, 64, 256);
    }

    // depthwise 3x3 + gelu gate -> gg (8 ch / thread)
    dw_kernel<<<M_TOT * 32 / 256, 256>>>(hid, fdw, gg);

    // ffn_out + residual -> out
    {
        dim3 g(M_TOT / 128, 1);
        gemm_tc<2, false><<<g, 256>>>(gg, fow, out, x2, M_TOT, 64, 128, 0);
    }
}

// round 7
// speedup vs baseline: 1.1992x; 1.1992x over previous
#include <cuda_runtime.h>
#include <cuda_bf16.h>
#include <mma.h>

using namespace nvcuda;

// ---------------------------------------------------------------------------
// Problem constants
// ---------------------------------------------------------------------------
#define NB      4
#define CDIM    64
#define HW      65536          // 256*256
#define NWIN    1024           // 4 * 16 * 16
#define DIN     128            // d_inner
#define NDBL    36             // dt_rank + 2*d_state
#define M_TOT   (NWIN * 256)   // 262144 token positions

// ---------------------------------------------------------------------------
// Scratch (static device globals — allocation-free per harness rules)
// ---------------------------------------------------------------------------
__device__ __align__(16) __nv_bfloat16 g_xw [M_TOT * CDIM];  // LN2 out, windowed
__device__ __align__(16) __nv_bfloat16 g_xz [M_TOT * 256];   // in_proj out (xm|z)
__device__ __align__(16) __nv_bfloat16 g_xc [M_TOT * DIN];   // conv+silu out
__device__ __align__(16) float         g_dbl[M_TOT * NDBL];  // x_proj out (dt|B|C)
__device__ __align__(16) __nv_bfloat16 g_y  [M_TOT * DIN];   // scan+gate out
__device__ __align__(16) float         g_x2 [NB * CDIM * HW];// x + attn (NCHW)
__device__ __align__(16) __nv_bfloat16 g_y2 [M_TOT * CDIM];  // LN3 out, pos-major
__device__ __align__(16) __nv_bfloat16 g_hid[M_TOT * 256];   // ffn_in out
__device__ __align__(16) __nv_bfloat16 g_g  [M_TOT * DIN];   // gelu(h1)*h2
__device__ float g_Atab[DIN * 16];
__device__ int   g_flag;

// ---------------------------------------------------------------------------
// prep: A table + structure flag (A[d][s] == -(s+1) fast path)
// ---------------------------------------------------------------------------
__global__ void prep_kernel(const float* __restrict__ alog,
                            float* __restrict__ Atab, int* __restrict__ flag)
{
    __shared__ int ok_s;
    if (threadIdx.x == 0) ok_s = 1;
    __syncthreads();
    bool ok = true;
    for (int i = threadIdx.x; i < DIN * 16; i += 256) {
        float a = -expf(alog[i]);
        Atab[i] = a;
        int s = i & 15;
        if (fabsf(a + (float)(s + 1)) > 1e-3f * (float)(s + 1)) ok = false;
    }
    if (!ok) atomicAnd(&ok_s, 0);
    __syncthreads();
    if (threadIdx.x == 0) *flag = ok_s;
}

// ---------------------------------------------------------------------------
// Channel LayerNorm -> bf16 (LN2 only: windowed layout (win*256+l, c)).
// ---------------------------------------------------------------------------
__global__ void __launch_bounds__(256) ln_kernel(
    const float* __restrict__ x, const float* __restrict__ gam,
    const float* __restrict__ bet, __nv_bfloat16* __restrict__ out)
{
    __shared__ float s[64][65];
    __shared__ float mu[64], rs[64];
    int tid  = threadIdx.x;
    int blk  = blockIdx.x;
    int bimg = blk >> 10;
    int rem  = blk & 1023;
    int h    = rem >> 2;
    int w0   = (rem & 3) << 6;
    const float* xb = x + ((bimg * CDIM) << 16) + (h << 8) + w0;

#pragma unroll
    for (int i = 0; i < 4; i++) {
        int idx = i * 256 + tid;          // 0..1023
        int c  = idx >> 4;
        int p4 = (idx & 15) << 2;
        float4 v = *(const float4*)&xb[(c << 16) + p4];
        s[p4 + 0][c] = v.x; s[p4 + 1][c] = v.y;
        s[p4 + 2][c] = v.z; s[p4 + 3][c] = v.w;
    }
    __syncthreads();
    if (tid < 64) {
        float sum = 0.f, sq = 0.f;
#pragma unroll
        for (int c = 0; c < 64; c++) { float v = s[tid][c]; sum += v; sq += v * v; }
        float m = sum * (1.f / 64.f);
        float var = sq * (1.f / 64.f) - m * m;
        mu[tid] = m;
        rs[tid] = rsqrtf(var + 1e-5f);
    }
    __syncthreads();
#pragma unroll
    for (int i = 0; i < 8; i++) {
        int idx = i * 256 + tid;          // 0..2047
        int p  = idx >> 5;
        int cp = (idx & 31) << 1;
        float m_ = mu[p], r_ = rs[p];
        float v0 = (s[p][cp]     - m_) * r_ * gam[cp]     + bet[cp];
        float v1 = (s[p][cp + 1] - m_) * r_ * gam[cp + 1] + bet[cp + 1];
        int wg = w0 + p;
        int win = (bimg << 8) + ((h >> 4) << 4) + (wg >> 4);
        int l   = ((h & 15) << 4) + (wg & 15);
        int pos = (win << 8) + l;
        *(__nv_bfloat162*)&out[(pos << 6) + cp] = __floats2bfloat162_rn(v0, v1);
    }
}

// ---------------------------------------------------------------------------
// Tensor-core GEMM: C[M,N] = A[M,K](bf16) @ W[N,K]^T(fp32->bf16)
// Block tile 128x64, 256 threads (8 warps, 4x2), warp tile 32x32, BK=64.
// EP 0: plain store (OUTBF: bf16 else fp32, guarded n<N)
// EP 2: ffn_out:  pos-major m -> NCHW scatter, C = res + acc (fp32)
// ---------------------------------------------------------------------------
template<int EP, bool OUTBF>
__global__ void __launch_bounds__(256) gemm_tc(
    const __nv_bfloat16* __restrict__ A, const float* __restrict__ W,
    void* __restrict__ Cout, const float* __restrict__ res,
    int M, int N, int K, int ldc)
{
    __shared__ __align__(16) unsigned char smem_raw[34816];
    __nv_bfloat16* As = (__nv_bfloat16*)smem_raw;   // [128][72]
    __nv_bfloat16* Ws = As + 128 * 72;              // [64][72]
    float* epi = (float*)smem_raw;                  // [128][68]

    int tid = threadIdx.x;
    int wid = tid >> 5;
    int wm = wid >> 1, wn = wid & 1;
    int m0 = blockIdx.x * 128;
    int n0 = blockIdx.y * 64;

    wmma::fragment<wmma::accumulator, 16, 16, 16, float> c[2][2];
#pragma unroll
    for (int i = 0; i < 2; i++)
#pragma unroll
        for (int j = 0; j < 2; j++) wmma::fill_fragment(c[i][j], 0.f);

    for (int k0 = 0; k0 < K; k0 += 64) {
#pragma unroll
        for (int i = 0; i < 4; i++) {
            int idx = tid + i * 256;
            int r = idx >> 3, v = idx & 7;
            *(uint4*)&As[r * 72 + v * 8] =
                *(const uint4*)&A[(m0 + r) * K + k0 + v * 8];
        }
#pragma unroll
        for (int i = 0; i < 4; i++) {
            int idx = tid + i * 256;
            int r = idx >> 4, v = idx & 15;
            float4 f = make_float4(0.f, 0.f, 0.f, 0.f);
            if (n0 + r < N) f = *(const float4*)&W[(n0 + r) * K + k0 + v * 4];
            __nv_bfloat16* dst = &Ws[r * 72 + v * 4];
            dst[0] = __float2bfloat16(f.x);
            dst[1] = __float2bfloat16(f.y);
            dst[2] = __float2bfloat16(f.z);
            dst[3] = __float2bfloat16(f.w);
        }
        __syncthreads();
#pragma unroll
        for (int kk = 0; kk < 64; kk += 16) {
            wmma::fragment<wmma::matrix_a, 16, 16, 16, __nv_bfloat16, wmma::row_major> a[2];
            wmma::fragment<wmma::matrix_b, 16, 16, 16, __nv_bfloat16, wmma::col_major> b[2];
#pragma unroll
            for (int i = 0; i < 2; i++)
                wmma::load_matrix_sync(a[i], &As[(wm * 32 + i * 16) * 72 + kk], 72);
#pragma unroll
            for (int j = 0; j < 2; j++)
                wmma::load_matrix_sync(b[j], &Ws[(wn * 32 + j * 16) * 72 + kk], 72);
#pragma unroll
            for (int i = 0; i < 2; i++)
#pragma unroll
                for (int j = 0; j < 2; j++)
                    wmma::mma_sync(c[i][j], a[i], b[j], c[i][j]);
        }
        __syncthreads();
    }

#pragma unroll
    for (int i = 0; i < 2; i++)
#pragma unroll
        for (int j = 0; j < 2; j++)
            wmma::store_matrix_sync(&epi[(wm * 32 + i * 16) * 68 + wn * 32 + j * 16],
                                    c[i][j], 68, wmma::mem_row_major);
    __syncthreads();

    if (EP == 0) {
        if (OUTBF) {
            __nv_bfloat16* Cb = (__nv_bfloat16*)Cout;
#pragma unroll
            for (int i = 0; i < 16; i++) {
                int idx = tid + i * 256;
                int r = idx >> 5, cp = (idx & 31) * 2;
                __nv_bfloat162 pk = __floats2bfloat162_rn(epi[r * 68 + cp],
                                                          epi[r * 68 + cp + 1]);
                *(__nv_bfloat162*)&Cb[(m0 + r) * ldc + n0 + cp] = pk;
            }
        } else {
            float* Cf = (float*)Cout;
#pragma unroll
            for (int i = 0; i < 32; i++) {
                int idx = tid + i * 256;
                int r = idx >> 6, cn = idx & 63;
                int n = n0 + cn;
                if (n < N) Cf[(m0 + r) * ldc + n] = epi[r * 68 + cn];
            }
        }
    } else {
        float* Cf = (float*)Cout;
#pragma unroll
        for (int i = 0; i < 32; i++) {
            int idx = tid + i * 256;
            int n = idx >> 7;
            int r = idx & 127;
            float v = epi[r * 68 + n];
            int m = m0 + r;
            int b = m >> 16, hw = m & 65535;
            int addr = ((b * CDIM + n) << 16) + hw;
            Cf[addr] = res[addr] + v;
        }
    }
}

// ---------------------------------------------------------------------------
// out_proj GEMM (M x 64, K=128) + residual + FUSED LayerNorm3.
// Writes x2 (fp32 NCHW) and y2 (bf16 pos-major).  Block = 128 rows x 64 cols.
// ---------------------------------------------------------------------------
__global__ void __launch_bounds__(256) gemm_out_ln(
    const __nv_bfloat16* __restrict__ A, const float* __restrict__ W,
    const float* __restrict__ res, const float* __restrict__ gam,
    const float* __restrict__ bet, float* __restrict__ x2,
    __nv_bfloat16* __restrict__ y2)
{
    __shared__ __align__(16) unsigned char smem_raw[34816];
    __nv_bfloat16* As = (__nv_bfloat16*)smem_raw;   // [128][72]
    __nv_bfloat16* Ws = As + 128 * 72;              // [64][72]
    float* epi = (float*)smem_raw;                  // [128][68]
    __shared__ float psum[128][2], psq[128][2], mu[128], rsd[128];

    int tid = threadIdx.x;
    int wid = tid >> 5;
    int wm = wid >> 1, wn = wid & 1;
    int m0 = blockIdx.x * 128;

    wmma::fragment<wmma::accumulator, 16, 16, 16, float> c[2][2];
#pragma unroll
    for (int i = 0; i < 2; i++)
#pragma unroll
        for (int j = 0; j < 2; j++) wmma::fill_fragment(c[i][j], 0.f);

    for (int k0 = 0; k0 < 128; k0 += 64) {
#pragma unroll
        for (int i = 0; i < 4; i++) {
            int idx = tid + i * 256;
            int r = idx >> 3, v = idx & 7;
            *(uint4*)&As[r * 72 + v * 8] =
                *(const uint4*)&A[(m0 + r) * 128 + k0 + v * 8];
        }
#pragma unroll
        for (int i = 0; i < 4; i++) {
            int idx = tid + i * 256;
            int r = idx >> 4, v = idx & 15;
            float4 f = *(const float4*)&W[r * 128 + k0 + v * 4];
            __nv_bfloat16* dst = &Ws[r * 72 + v * 4];
            dst[0] = __float2bfloat16(f.x);
            dst[1] = __float2bfloat16(f.y);
            dst[2] = __float2bfloat16(f.z);
            dst[3] = __float2bfloat16(f.w);
        }
        __syncthreads();
#pragma unroll
        for (int kk = 0; kk < 64; kk += 16) {
            wmma::fragment<wmma::matrix_a, 16, 16, 16, __nv_bfloat16, wmma::row_major> a[2];
            wmma::fragment<wmma::matrix_b, 16, 16, 16, __nv_bfloat16, wmma::col_major> b[2];
#pragma unroll
            for (int i = 0; i < 2; i++)
                wmma::load_matrix_sync(a[i], &As[(wm * 32 + i * 16) * 72 + kk], 72);
#pragma unroll
            for (int j = 0; j < 2; j++)
                wmma::load_matrix_sync(b[j], &Ws[(wn * 32 + j * 16) * 72 + kk], 72);
#pragma unroll
            for (int i = 0; i < 2; i++)
#pragma unroll
                for (int j = 0; j < 2; j++)
                    wmma::mma_sync(c[i][j], a[i], b[j], c[i][j]);
        }
        __syncthreads();
    }

#pragma unroll
    for (int i = 0; i < 2; i++)
#pragma unroll
        for (int j = 0; j < 2; j++)
            wmma::store_matrix_sync(&epi[(wm * 32 + i * 16) * 68 + wn * 32 + j * 16],
                                    c[i][j], 68, wmma::mem_row_major);
    __syncthreads();

    // Epilogue: residual add + x2 store + LN over 64 channels + y2 store.
    int r = tid & 127, half = tid >> 7;
    int m = m0 + r;
    int win = m >> 8, l = m & 255;
    int b = win >> 8, widx = win & 255;
    int h = ((widx >> 4) << 4) + (l >> 4);
    int w = ((widx & 15) << 4) + (l & 15);
    int pos = (b << 16) + (h << 8) + w;

    float sum = 0.f, sq = 0.f;
#pragma unroll
    for (int ch = 0; ch < 32; ch++) {
        int n = half * 32 + ch;
        int addr = ((b * CDIM + n) << 16) + (h << 8) + w;
        float v = res[addr] + epi[r * 68 + n];
        x2[addr] = v;
        epi[r * 68 + n] = v;
        sum += v; sq += v * v;
    }
    psum[r][half] = sum;
    psq[r][half] = sq;
    __syncthreads();
    if (tid < 128) {
        float s = psum[tid][0] + psum[tid][1];
        float q = psq[tid][0] + psq[tid][1];
        float m_ = s * (1.f / 64.f);
        mu[tid] = m_;
        rsd[tid] = rsqrtf(q * (1.f / 64.f) - m_ * m_ + 1e-5f);
    }
    __syncthreads();
    {
        float m_ = mu[r], r_ = rsd[r];
        uint4 pk[4];
        __nv_bfloat162* pp = (__nv_bfloat162*)pk;
#pragma unroll
        for (int q2 = 0; q2 < 16; q2++) {
            int n = half * 32 + q2 * 2;
            float v0 = (epi[r * 68 + n]     - m_) * r_ * gam[n]     + bet[n];
            float v1 = (epi[r * 68 + n + 1] - m_) * r_ * gam[n + 1] + bet[n + 1];
            pp[q2] = __floats2bfloat162_rn(v0, v1);
        }
#pragma unroll
        for (int q4 = 0; q4 < 4; q4++)
            *(uint4*)&y2[(pos << 6) + half * 32 + q4 * 8] = pk[q4];
    }
}

// ---------------------------------------------------------------------------
// Depthwise causal conv1d (k=4, pad 3) + bias + SiLU.
// Thread = bf16x2 channel pair of one position (warp = 64 consecutive ch).
// ---------------------------------------------------------------------------
__global__ void __launch_bounds__(256) conv_kernel(
    const __nv_bfloat16* __restrict__ xz, const float* __restrict__ cw,
    const float* __restrict__ cb, __nv_bfloat16* __restrict__ xc)
{
    int gid = blockIdx.x * 256 + threadIdx.x;   // M_TOT*64 total
    int dp = gid & 63;
    int m  = gid >> 6;
    int t  = m & 255;
    int d0 = dp << 1;

    float a0 = cb[d0], a1 = cb[d0 + 1];
    float4 w0 = *(const float4*)&cw[d0 << 2];
    float4 w1 = *(const float4*)&cw[(d0 + 1) << 2];
    float wA[4] = {w0.x, w0.y, w0.z, w0.w};
    float wB[4] = {w1.x, w1.y, w1.z, w1.w};

#pragma unroll
    for (int j = 0; j < 4; j++) {
        if (t - 3 + j >= 0) {
            float2 f = __bfloat1622float2(
                *(const __nv_bfloat162*)&xz[((m - 3 + j) << 8) + d0]);
            a0 = fmaf(wA[j], f.x, a0);
            a1 = fmaf(wB[j], f.y, a1);
        }
    }
    float s0 = __fdividef(a0, 1.f + __expf(-a0));
    float s1 = __fdividef(a1, 1.f + __expf(-a1));
    *(__nv_bfloat162*)&xc[(m << 7) + d0] = __floats2bfloat162_rn(s0, s1);
}

// ---------------------------------------------------------------------------
// Selective scan + fused dt_proj/softplus + D skip + SiLU(z) gate.
// ---------------------------------------------------------------------------
__global__ void __launch_bounds__(128) scan_kernel(
    const float* __restrict__ dbl, const __nv_bfloat16* __restrict__ xc,
    const __nv_bfloat16* __restrict__ xz, const float* __restrict__ dtw,
    const float* __restrict__ dtb, const float* __restrict__ Dv,
    const float* __restrict__ Atab, const int* __restrict__ flagp,
    __nv_bfloat16* __restrict__ yout)
{
    int win = blockIdx.x;
    int d = threadIdx.x;
    int fl = *flagp;
    float Dd = Dv[d];
    float4 wv = *(const float4*)&dtw[d << 2];
    float bb = dtb[d];
    float h[16];
#pragma unroll
    for (int s = 0; s < 16; s++) h[s] = 0.f;
    int mbase = win << 8;

    for (int t = 0; t < 256; t++) {
        int m = mbase + t;
        const float* row = dbl + m * NDBL;
        float4 q = *(const float4*)row;
        float pre = bb + q.x * wv.x + q.y * wv.y + q.z * wv.z + q.w * wv.w;
        float dtv = (pre > 15.f) ? pre : log1pf(__expf(pre));
        float u  = __bfloat162float(xc[(m << 7) + d]);
        float zv = __bfloat162float(xz[(m << 8) + 128 + d]);
        float4 B0 = *(const float4*)(row + 4);
        float4 B1 = *(const float4*)(row + 8);
        float4 B2 = *(const float4*)(row + 12);
        float4 B3 = *(const float4*)(row + 16);
        float4 C0 = *(const float4*)(row + 20);
        float4 C1 = *(const float4*)(row + 24);
        float4 C2 = *(const float4*)(row + 28);
        float4 C3 = *(const float4*)(row + 32);
        float Bv[16] = {B0.x,B0.y,B0.z,B0.w, B1.x,B1.y,B1.z,B1.w,
                        B2.x,B2.y,B2.z,B2.w, B3.x,B3.y,B3.z,B3.w};
        float Cv[16] = {C0.x,C0.y,C0.z,C0.w, C1.x,C1.y,C1.z,C1.w,
                        C2.x,C2.y,C2.z,C2.w, C3.x,C3.y,C3.z,C3.w};
        float dtu = dtv * u;
        float yv = 0.f;
        if (fl) {
            float r = __expf(-dtv);
            float p = r;
#pragma unroll
            for (int s = 0; s < 16; s++) {
                h[s] = h[s] * p + dtu * Bv[s];
                yv += h[s] * Cv[s];
                p *= r;
            }
        } else {
#pragma unroll
            for (int s = 0; s < 16; s++) {
                float dec = __expf(dtv * Atab[(d << 4) + s]);
                h[s] = h[s] * dec + dtu * Bv[s];
                yv += h[s] * Cv[s];
            }
        }
        yv += u * Dd;
        float sg = __fdividef(1.f, 1.f + __expf(-zv));
        yout[(m << 7) + d] = __float2bfloat16(yv * zv * sg);
    }
}

// ---------------------------------------------------------------------------
// Depthwise 3x3 SAME conv + exact-GELU gate (4+4 channels / thread).
// ---------------------------------------------------------------------------
__global__ void __launch_bounds__(256) dw_kernel(
    const __nv_bfloat16* __restrict__ hid, const float* __restrict__ dww,
    __nv_bfloat16* __restrict__ gout)
{
    __shared__ float wsm[256 * 9];
    int tid = threadIdx.x;
#pragma unroll
    for (int i = 0; i < 9; i++) wsm[i * 256 + tid] = dww[i * 256 + tid];
    __syncthreads();

    int gid = blockIdx.x * 256 + tid;     // M_TOT*32 total
    int j = gid & 31;
    int m = gid >> 5;
    int c0 = j << 2;
    int b = m >> 16, hw = m & 65535;
    int h = hw >> 8, w = hw & 255;

    float a1[4] = {0.f, 0.f, 0.f, 0.f};
    float a2[4] = {0.f, 0.f, 0.f, 0.f};

#pragma unroll
    for (int dy = 0; dy < 3; dy++) {
        int hh = h + dy - 1;
        if (hh < 0 || hh > 255) continue;
#pragma unroll
        for (int dx = 0; dx < 3; dx++) {
            int ww = w + dx - 1;
            if (ww < 0 || ww > 255) continue;
            int mm = (b << 16) + (hh << 8) + ww;
            const __nv_bfloat16* rowp = hid + (mm << 8);
            uint2 r1 = *(const uint2*)&rowp[c0];
            uint2 r2 = *(const uint2*)&rowp[c0 + 128];
            float2 f1a = __bfloat1622float2(((const __nv_bfloat162*)&r1)[0]);
            float2 f1b = __bfloat1622float2(((const __nv_bfloat162*)&r1)[1]);
            float2 f2a = __bfloat1622float2(((const __nv_bfloat162*)&r2)[0]);
            float2 f2b = __bfloat1622float2(((const __nv_bfloat162*)&r2)[1]);
            int k = dy * 3 + dx;
            a1[0] = fmaf(wsm[(c0 + 0) * 9 + k], f1a.x, a1[0]);
            a1[1] = fmaf(wsm[(c0 + 1) * 9 + k], f1a.y, a1[1]);
            a1[2] = fmaf(wsm[(c0 + 2) * 9 + k], f1b.x, a1[2]);
            a1[3] = fmaf(wsm[(c0 + 3) * 9 + k], f1b.y, a1[3]);
            a2[0] = fmaf(wsm[(c0 + 128) * 9 + k], f2a.x, a2[0]);
            a2[1] = fmaf(wsm[(c0 + 129) * 9 + k], f2a.y, a2[1]);
            a2[2] = fmaf(wsm[(c0 + 130) * 9 + k], f2b.x, a2[2]);
            a2[3] = fmaf(wsm[(c0 + 131) * 9 + k], f2b.y, a2[3]);
        }
    }

    uint2 outv;
    __nv_bfloat162* op = (__nv_bfloat162*)&outv;
#pragma unroll
    for (int q = 0; q < 2; q++) {
        float g0 = 0.5f * a1[q * 2]     * (1.f + erff(a1[q * 2]     * 0.70710678118f));
        float g1 = 0.5f * a1[q * 2 + 1] * (1.f + erff(a1[q * 2 + 1] * 0.70710678118f));
        op[q] = __floats2bfloat162_rn(g0 * a2[q * 2], g1 * a2[q * 2 + 1]);
    }
    *(uint2*)&gout[(m << 7) + c0] = outv;
}

// ---------------------------------------------------------------------------
// launch
// ---------------------------------------------------------------------------
extern "C" void kernel_launch(void* const* d_in, const int* in_sizes, int n_in,
                              void* d_out, int out_size)
{
    (void)in_sizes; (void)n_in; (void)out_size;
    const float* x     = (const float*)d_in[0];
    const float* ln2w  = (const float*)d_in[1];
    const float* ln2b  = (const float*)d_in[2];
    const float* ln3w  = (const float*)d_in[3];
    const float* ln3b  = (const float*)d_in[4];
    const float* inpw  = (const float*)d_in[5];
    const float* convw = (const float*)d_in[6];
    const float* convb = (const float*)d_in[7];
    const float* xpw   = (const float*)d_in[8];
    const float* dtw   = (const float*)d_in[9];
    const float* dtb   = (const float*)d_in[10];
    const float* alog  = (const float*)d_in[11];
    const float* Dv    = (const float*)d_in[12];
    const float* outw  = (const float*)d_in[13];
    const float* fiw   = (const float*)d_in[14];
    const float* fdw   = (const float*)d_in[15];
    const float* fow   = (const float*)d_in[16];
    float* out = (float*)d_out;

    __nv_bfloat16 *xw, *xz, *xc, *yb, *y2, *hid, *gg;
    float *dbl, *x2, *Atab;
    int* flag;
    cudaGetSymbolAddress((void**)&xw,  g_xw);
    cudaGetSymbolAddress((void**)&xz,  g_xz);
    cudaGetSymbolAddress((void**)&xc,  g_xc);
    cudaGetSymbolAddress((void**)&dbl, g_dbl);
    cudaGetSymbolAddress((void**)&yb,  g_y);
    cudaGetSymbolAddress((void**)&x2,  g_x2);
    cudaGetSymbolAddress((void**)&y2,  g_y2);
    cudaGetSymbolAddress((void**)&hid, g_hid);
    cudaGetSymbolAddress((void**)&gg,  g_g);
    cudaGetSymbolAddress((void**)&Atab, g_Atab);
    cudaGetSymbolAddress((void**)&flag, g_flag);

    prep_kernel<<<1, 256>>>(alog, Atab, flag);

    // LN2 + window partition -> bf16
    ln_kernel<<<4096, 256>>>(x, ln2w, ln2b, xw);

    // in_proj: (262144,64) @ (256,64)^T -> xz (bf16)
    {
        dim3 g(M_TOT / 128, 4);
        gemm_tc<0, true><<<g, 256>>>(xw, inpw, xz, nullptr, M_TOT, 256, 64, 256);
    }

    // depthwise causal conv1d + silu (2 ch / thread)
    conv_kernel<<<M_TOT * 64 / 256, 256>>>(xz, convw, convb, xc);

    // x_proj: (262144,128) @ (36,128)^T -> dbl (fp32)
    {
        dim3 g(M_TOT / 128, 1);
        gemm_tc<0, false><<<g, 256>>>(xc, xpw, dbl, nullptr, M_TOT, NDBL, 128, NDBL);
    }

    // selective scan (fused dt_proj+softplus) + D skip + silu(z) gate
    scan_kernel<<<NWIN, 128>>>(dbl, xc, xz, dtw, dtb, Dv, Atab, flag, yb);

    // out_proj + un-window + residual + FUSED LN3 -> x2 (fp32), y2 (bf16)
    gemm_out_ln<<<M_TOT / 128, 256>>>(yb, outw, x, ln3w, ln3b, x2, y2);

    // ffn_in: (262144,64) @ (256,64)^T -> hid (bf16)
    {
        dim3 g(M_TOT / 128, 4);
        gemm_tc<0, true><<<g, 256>>>(y2, fiw, hid, nullptr, M_TOT, 256, 64, 256);
    }

    // depthwise 3x3 + gelu gate -> gg
    dw_kernel<<<M_TOT * 32 / 256, 256>>>(hid, fdw, gg);

    // ffn_out + residual -> out
    {
        dim3 g(M_TOT / 128, 1);
        gemm_tc<2, false><<<g, 256>>>(gg, fow, out, x2, M_TOT, 64, 128, 0);
    }
}